// round 1
// baseline (speedup 1.0000x reference)
#include <cuda_runtime.h>
#include <cuda_bf16.h>

static const int NN = 200000;
static const int NE = 3200000;
static const int NG = 400;

// Scratch (device globals; no runtime allocation allowed)
__device__ float g_deg[NN];
__device__ float g_bufA[(size_t)NN * 128];  // holds layer0 out (128), layer2 out (28)
__device__ float g_bufB[(size_t)NN * 48];   // holds layer1 out (48), layer3 out (5)
__device__ float g_agg[(size_t)NN * 128];   // neighbor-sum scratch (max d_in = 128)
__device__ float g_cnt[NG];

// ---------------------------------------------------------------------------
// degree: deg[v] = #in-edges
__global__ void k_degree(const int* __restrict__ dst) {
    int e = blockIdx.x * blockDim.x + threadIdx.x;
    if (e < NE) atomicAdd(&g_deg[dst[e]], 1.0f);
}

// ---------------------------------------------------------------------------
// edge scatter: agg[dst] += h[src], float4-vectorized over features
template <int DIN>
__global__ void k_scatter(const float* __restrict__ h,
                          const int* __restrict__ src,
                          const int* __restrict__ dst,
                          float* __restrict__ agg) {
    constexpr int D4 = DIN / 4;
    long long idx = (long long)blockIdx.x * blockDim.x + threadIdx.x;
    long long total = (long long)NE * D4;
    if (idx >= total) return;
    int e = (int)(idx / D4);
    int q = (int)(idx % D4);
    int s = src[e];
    int d = dst[e];
    float4 v = reinterpret_cast<const float4*>(h + (size_t)s * DIN)[q];
    float* a = agg + (size_t)d * DIN + q * 4;
    atomicAdd(a + 0, v.x);
    atomicAdd(a + 1, v.y);
    atomicAdd(a + 2, v.z);
    atomicAdd(a + 3, v.w);
}

// ---------------------------------------------------------------------------
// fused SAGE projection: out[v,o] = (relu)( h[v]@Ws + (agg[v]/max(deg,1))@Wn + b )
template <int DIN, int DOUT, bool RELU>
__global__ void k_sage(const float* __restrict__ hin,
                       const float* __restrict__ agg,
                       const float* __restrict__ Ws,
                       const float* __restrict__ Wn,
                       const float* __restrict__ bias,
                       float* __restrict__ hout) {
    long long idx = (long long)blockIdx.x * blockDim.x + threadIdx.x;
    long long total = (long long)NN * DOUT;
    if (idx >= total) return;
    int v = (int)(idx / DOUT);
    int o = (int)(idx % DOUT);
    float inv = 1.0f / fmaxf(g_deg[v], 1.0f);
    float acc = bias[o];
    const float* hrow = hin + (size_t)v * DIN;
    const float* arow = agg + (size_t)v * DIN;
#pragma unroll
    for (int k = 0; k < DIN; k++) {
        acc = fmaf(hrow[k], Ws[k * DOUT + o], acc);
        acc = fmaf(arow[k] * inv, Wn[k * DOUT + o], acc);
    }
    hout[idx] = RELU ? fmaxf(acc, 0.0f) : acc;
}

// ---------------------------------------------------------------------------
// readout: per-graph mean of final node features (d=5)
__global__ void k_cnt(const int* __restrict__ gid) {
    int v = blockIdx.x * blockDim.x + threadIdx.x;
    if (v < NN) atomicAdd(&g_cnt[gid[v]], 1.0f);
}

__global__ void k_accum(const float* __restrict__ h,
                        const int* __restrict__ gid,
                        float* __restrict__ out) {
    int idx = blockIdx.x * blockDim.x + threadIdx.x;
    if (idx >= NN * 5) return;
    int v = idx / 5;
    int f = idx % 5;
    atomicAdd(&out[gid[v] * 5 + f], h[idx]);
}

__global__ void k_final(float* __restrict__ out) {
    int i = blockIdx.x * blockDim.x + threadIdx.x;
    if (i < NG * 5) out[i] /= fmaxf(g_cnt[i / 5], 1.0f);
}

// ---------------------------------------------------------------------------
static inline int blks(long long n, int t) { return (int)((n + t - 1) / t); }

extern "C" void kernel_launch(void* const* d_in, const int* in_sizes, int n_in,
                              void* d_out, int out_size) {
    const float* feat = (const float*)d_in[0];
    const int* src = (const int*)d_in[1];
    const int* dst = (const int*)d_in[2];
    const int* gid = (const int*)d_in[3];
    const float* Ws0 = (const float*)d_in[4];
    const float* Wn0 = (const float*)d_in[5];
    const float* b0  = (const float*)d_in[6];
    const float* Ws1 = (const float*)d_in[7];
    const float* Wn1 = (const float*)d_in[8];
    const float* b1  = (const float*)d_in[9];
    const float* Ws2 = (const float*)d_in[10];
    const float* Wn2 = (const float*)d_in[11];
    const float* b2  = (const float*)d_in[12];
    const float* Ws3 = (const float*)d_in[13];
    const float* Wn3 = (const float*)d_in[14];
    const float* b3  = (const float*)d_in[15];
    float* out = (float*)d_out;

    float *deg, *bufA, *bufB, *agg, *cnt;
    cudaGetSymbolAddress((void**)&deg, g_deg);
    cudaGetSymbolAddress((void**)&bufA, g_bufA);
    cudaGetSymbolAddress((void**)&bufB, g_bufB);
    cudaGetSymbolAddress((void**)&agg, g_agg);
    cudaGetSymbolAddress((void**)&cnt, g_cnt);

    const int T = 256;

    // degree (shared by all layers)
    cudaMemsetAsync(deg, 0, NN * sizeof(float));
    k_degree<<<blks(NE, T), T>>>(dst);

    // ---- layer 0: 32 -> 128, relu ----
    cudaMemsetAsync(agg, 0, (size_t)NN * 32 * sizeof(float));
    k_scatter<32><<<blks((long long)NE * 8, T), T>>>(feat, src, dst, agg);
    k_sage<32, 128, true><<<blks((long long)NN * 128, T), T>>>(feat, agg, Ws0, Wn0, b0, bufA);

    // ---- layer 1: 128 -> 48, relu ----
    cudaMemsetAsync(agg, 0, (size_t)NN * 128 * sizeof(float));
    k_scatter<128><<<blks((long long)NE * 32, T), T>>>(bufA, src, dst, agg);
    k_sage<128, 48, true><<<blks((long long)NN * 48, T), T>>>(bufA, agg, Ws1, Wn1, b1, bufB);

    // ---- layer 2: 48 -> 28, relu ----
    cudaMemsetAsync(agg, 0, (size_t)NN * 48 * sizeof(float));
    k_scatter<48><<<blks((long long)NE * 12, T), T>>>(bufB, src, dst, agg);
    k_sage<48, 28, true><<<blks((long long)NN * 28, T), T>>>(bufB, agg, Ws2, Wn2, b2, bufA);

    // ---- layer 3: 28 -> 5, linear ----
    cudaMemsetAsync(agg, 0, (size_t)NN * 28 * sizeof(float));
    k_scatter<28><<<blks((long long)NE * 7, T), T>>>(bufA, src, dst, agg);
    k_sage<28, 5, false><<<blks((long long)NN * 5, T), T>>>(bufA, agg, Ws3, Wn3, b3, bufB);

    // ---- readout: per-graph mean ----
    cudaMemsetAsync(out, 0, NG * 5 * sizeof(float));
    cudaMemsetAsync(cnt, 0, NG * sizeof(float));
    k_cnt<<<blks(NN, T), T>>>(gid);
    k_accum<<<blks((long long)NN * 5, T), T>>>(bufB, gid, out);
    k_final<<<blks(NG * 5, T), T>>>(out);
}

// round 2
// speedup vs baseline: 1.6641x; 1.6641x over previous
#include <cuda_runtime.h>
#include <cuda_bf16.h>

static const int NN = 200000;
static const int NE = 3200000;
static const int NG = 400;

// Scratch (device globals; no runtime allocation allowed)
__device__ int   g_degi[NN];
__device__ int   g_off[NN + 1];
__device__ int   g_cursor[NN];
__device__ int   g_csr[NE];
__device__ float g_bufA[(size_t)NN * 128];  // layer0 out (128), layer2 out (28)
__device__ float g_bufB[(size_t)NN * 48];   // layer1 out (48), layer3 out (5)
__device__ float g_z[(size_t)NN * 48];      // projected features (pre-aggregation)
__device__ float g_agg[(size_t)NN * 48];    // normalized neighbor aggregate
__device__ float g_cnt[NG];

// ---------------------------------------------------------------------------
__global__ void k_degree(const int* __restrict__ dst) {
    int e = blockIdx.x * blockDim.x + threadIdx.x;
    if (e < NE) atomicAdd(&g_degi[dst[e]], 1);
}

// single-block exclusive scan of g_degi -> g_off (NN+1 entries)
__global__ void k_scan() {
    const int T = 1024;
    const int ITEMS = (NN + T) / T;  // 196
    __shared__ int part[T];
    int t = threadIdx.x;
    int base = t * ITEMS;
    int s = 0;
#pragma unroll 4
    for (int i = 0; i < ITEMS; i++) {
        int j = base + i;
        if (j < NN) s += g_degi[j];
    }
    part[t] = s;
    __syncthreads();
    for (int d = 1; d < T; d <<= 1) {
        int v = 0;
        if (t >= d) v = part[t - d];
        __syncthreads();
        if (t >= d) part[t] += v;
        __syncthreads();
    }
    int run = (t == 0) ? 0 : part[t - 1];
    for (int i = 0; i < ITEMS; i++) {
        int j = base + i;
        if (j <= NN) g_off[j] = run;
        if (j < NN) run += g_degi[j];
    }
}

__global__ void k_build(const int* __restrict__ src, const int* __restrict__ dst) {
    int e = blockIdx.x * blockDim.x + threadIdx.x;
    if (e >= NE) return;
    int p = atomicAdd(&g_cursor[dst[e]], 1);
    g_csr[p] = src[e];
}

// ---------------------------------------------------------------------------
// warp-per-node CSR gather with mean normalization: agg[v] = (1/max(deg,1)) * sum z[src]
template <int DIM>
__global__ void k_gather(const float* __restrict__ z, float* __restrict__ agg) {
    int gt = blockIdx.x * blockDim.x + threadIdx.x;
    int v = gt >> 5;
    int lane = gt & 31;
    if (v >= NN) return;
    int beg = g_off[v];
    int end = g_off[v + 1];
    constexpr int R = (DIM + 31) / 32;
    float acc[R];
#pragma unroll
    for (int r = 0; r < R; r++) acc[r] = 0.0f;

    int e = beg;
    for (; e + 2 <= end; e += 2) {
        int s0 = g_csr[e];
        int s1 = g_csr[e + 1];
        const float* r0 = z + (size_t)s0 * DIM;
        const float* r1 = z + (size_t)s1 * DIM;
#pragma unroll
        for (int r = 0; r < R; r++) {
            int f = lane + 32 * r;
            if (f < DIM) acc[r] += r0[f] + r1[f];
        }
    }
    if (e < end) {
        int s0 = g_csr[e];
        const float* r0 = z + (size_t)s0 * DIM;
#pragma unroll
        for (int r = 0; r < R; r++) {
            int f = lane + 32 * r;
            if (f < DIM) acc[r] += r0[f];
        }
    }
    float inv = 1.0f / fmaxf((float)(end - beg), 1.0f);
#pragma unroll
    for (int r = 0; r < R; r++) {
        int f = lane + 32 * r;
        if (f < DIM) agg[(size_t)v * DIM + f] = acc[r] * inv;
    }
}

// ---------------------------------------------------------------------------
// z = h @ Wn (plain projection)
template <int DIN, int DOUT>
__global__ void k_gemm(const float* __restrict__ h, const float* __restrict__ W,
                       float* __restrict__ z) {
    long long idx = (long long)blockIdx.x * blockDim.x + threadIdx.x;
    if (idx >= (long long)NN * DOUT) return;
    int v = (int)(idx / DOUT);
    int o = (int)(idx % DOUT);
    const float* hrow = h + (size_t)v * DIN;
    float acc = 0.0f;
#pragma unroll
    for (int k = 0; k < DIN; k++) acc = fmaf(hrow[k], W[k * DOUT + o], acc);
    z[idx] = acc;
}

// out = act(h@Ws + aggn + b)  (aggn already projected+normalized)
template <int DIN, int DOUT, bool RELU>
__global__ void k_post(const float* __restrict__ h, const float* __restrict__ aggn,
                       const float* __restrict__ Ws, const float* __restrict__ bias,
                       float* __restrict__ out) {
    long long idx = (long long)blockIdx.x * blockDim.x + threadIdx.x;
    if (idx >= (long long)NN * DOUT) return;
    int v = (int)(idx / DOUT);
    int o = (int)(idx % DOUT);
    const float* hrow = h + (size_t)v * DIN;
    float acc = bias[o] + aggn[idx];
#pragma unroll
    for (int k = 0; k < DIN; k++) acc = fmaf(hrow[k], Ws[k * DOUT + o], acc);
    out[idx] = RELU ? fmaxf(acc, 0.0f) : acc;
}

// layer-0 form: out = relu(h@Ws + aggn@Wn + b)  (aggn is normalized raw-feature aggregate)
template <int DIN, int DOUT, bool RELU>
__global__ void k_sageA(const float* __restrict__ h, const float* __restrict__ aggn,
                        const float* __restrict__ Ws, const float* __restrict__ Wn,
                        const float* __restrict__ bias, float* __restrict__ out) {
    long long idx = (long long)blockIdx.x * blockDim.x + threadIdx.x;
    if (idx >= (long long)NN * DOUT) return;
    int v = (int)(idx / DOUT);
    int o = (int)(idx % DOUT);
    const float* hrow = h + (size_t)v * DIN;
    const float* arow = aggn + (size_t)v * DIN;
    float acc = bias[o];
#pragma unroll
    for (int k = 0; k < DIN; k++) {
        acc = fmaf(hrow[k], Ws[k * DOUT + o], acc);
        acc = fmaf(arow[k], Wn[k * DOUT + o], acc);
    }
    out[idx] = RELU ? fmaxf(acc, 0.0f) : acc;
}

// ---------------------------------------------------------------------------
__global__ void k_cnt(const int* __restrict__ gid) {
    int v = blockIdx.x * blockDim.x + threadIdx.x;
    if (v < NN) atomicAdd(&g_cnt[gid[v]], 1.0f);
}

__global__ void k_accum(const float* __restrict__ h, const int* __restrict__ gid,
                        float* __restrict__ out) {
    int idx = blockIdx.x * blockDim.x + threadIdx.x;
    if (idx >= NN * 5) return;
    atomicAdd(&out[gid[idx / 5] * 5 + (idx % 5)], h[idx]);
}

__global__ void k_final(float* __restrict__ out) {
    int i = blockIdx.x * blockDim.x + threadIdx.x;
    if (i < NG * 5) out[i] /= fmaxf(g_cnt[i / 5], 1.0f);
}

// ---------------------------------------------------------------------------
static inline int blks(long long n, int t) { return (int)((n + t - 1) / t); }

extern "C" void kernel_launch(void* const* d_in, const int* in_sizes, int n_in,
                              void* d_out, int out_size) {
    const float* feat = (const float*)d_in[0];
    const int* src = (const int*)d_in[1];
    const int* dst = (const int*)d_in[2];
    const int* gid = (const int*)d_in[3];
    const float* Ws0 = (const float*)d_in[4];
    const float* Wn0 = (const float*)d_in[5];
    const float* b0  = (const float*)d_in[6];
    const float* Ws1 = (const float*)d_in[7];
    const float* Wn1 = (const float*)d_in[8];
    const float* b1  = (const float*)d_in[9];
    const float* Ws2 = (const float*)d_in[10];
    const float* Wn2 = (const float*)d_in[11];
    const float* b2  = (const float*)d_in[12];
    const float* Ws3 = (const float*)d_in[13];
    const float* Wn3 = (const float*)d_in[14];
    const float* b3  = (const float*)d_in[15];
    float* out = (float*)d_out;

    float *bufA, *bufB, *z, *agg, *cnt;
    int *degi, *off, *cursor;
    cudaGetSymbolAddress((void**)&bufA, g_bufA);
    cudaGetSymbolAddress((void**)&bufB, g_bufB);
    cudaGetSymbolAddress((void**)&z, g_z);
    cudaGetSymbolAddress((void**)&agg, g_agg);
    cudaGetSymbolAddress((void**)&cnt, g_cnt);
    cudaGetSymbolAddress((void**)&degi, g_degi);
    cudaGetSymbolAddress((void**)&off, g_off);
    cudaGetSymbolAddress((void**)&cursor, g_cursor);

    const int T = 256;

    // ---- CSR build (per call; deterministic work) ----
    cudaMemsetAsync(degi, 0, NN * sizeof(int));
    k_degree<<<blks(NE, T), T>>>(dst);
    k_scan<<<1, 1024>>>();
    cudaMemcpyAsync(cursor, off, NN * sizeof(int), cudaMemcpyDeviceToDevice);
    k_build<<<blks(NE, T), T>>>(src, dst);

    // ---- layer 0: 32 -> 128, relu (aggregate raw feats: 32 < 128) ----
    k_gather<32><<<blks((long long)NN * 32, T), T>>>(feat, agg);
    k_sageA<32, 128, true><<<blks((long long)NN * 128, T), T>>>(feat, agg, Ws0, Wn0, b0, bufA);

    // ---- layer 1: 128 -> 48, relu (project first: 48 < 128) ----
    k_gemm<128, 48><<<blks((long long)NN * 48, T), T>>>(bufA, Wn1, z);
    k_gather<48><<<blks((long long)NN * 32, T), T>>>(z, agg);
    k_post<128, 48, true><<<blks((long long)NN * 48, T), T>>>(bufA, agg, Ws1, b1, bufB);

    // ---- layer 2: 48 -> 28, relu ----
    k_gemm<48, 28><<<blks((long long)NN * 28, T), T>>>(bufB, Wn2, z);
    k_gather<28><<<blks((long long)NN * 32, T), T>>>(z, agg);
    k_post<48, 28, true><<<blks((long long)NN * 28, T), T>>>(bufB, agg, Ws2, b2, bufA);

    // ---- layer 3: 28 -> 5, linear ----
    k_gemm<28, 5><<<blks((long long)NN * 5, T), T>>>(bufA, Wn3, z);
    k_gather<5><<<blks((long long)NN * 32, T), T>>>(z, agg);
    k_post<28, 5, false><<<blks((long long)NN * 5, T), T>>>(bufA, agg, Ws3, b3, bufB);

    // ---- readout ----
    cudaMemsetAsync(out, 0, NG * 5 * sizeof(float));
    cudaMemsetAsync(cnt, 0, NG * sizeof(float));
    k_cnt<<<blks(NN, T), T>>>(gid);
    k_accum<<<blks((long long)NN * 5, T), T>>>(bufB, gid, out);
    k_final<<<blks(NG * 5, T), T>>>(out);
}

// round 3
// speedup vs baseline: 3.2564x; 1.9568x over previous
#include <cuda_runtime.h>
#include <cuda_bf16.h>

static const int NN = 200000;
static const int NE = 3200000;
static const int NG = 400;

// Scratch (device globals; no runtime allocation allowed)
__device__ int   g_degi[NN];
__device__ int   g_off[NN + 1];
__device__ int   g_cursor[NN];
__device__ int   g_csr[NE];
__device__ float g_bufA[(size_t)NN * 128];  // layer0 out (128), layer2 out (28)
__device__ float g_bufB[(size_t)NN * 48];   // layer1 out (48), layer3 out (5)
__device__ float g_z[(size_t)NN * 48];      // projected features (pre-aggregation)
__device__ float g_agg[(size_t)NN * 48];    // normalized neighbor aggregate
__device__ float g_cnt[NG];

// ---------------------------------------------------------------------------
__global__ void k_degree(const int* __restrict__ dst) {
    int e = blockIdx.x * blockDim.x + threadIdx.x;
    if (e < NE) atomicAdd(&g_degi[dst[e]], 1);
}

// single-block exclusive scan of g_degi -> g_off (NN+1 entries)
__global__ void k_scan() {
    const int T = 1024;
    const int ITEMS = (NN + T) / T;
    __shared__ int part[T];
    int t = threadIdx.x;
    int base = t * ITEMS;
    int s = 0;
#pragma unroll 4
    for (int i = 0; i < ITEMS; i++) {
        int j = base + i;
        if (j < NN) s += g_degi[j];
    }
    part[t] = s;
    __syncthreads();
    for (int d = 1; d < T; d <<= 1) {
        int v = 0;
        if (t >= d) v = part[t - d];
        __syncthreads();
        if (t >= d) part[t] += v;
        __syncthreads();
    }
    int run = (t == 0) ? 0 : part[t - 1];
    for (int i = 0; i < ITEMS; i++) {
        int j = base + i;
        if (j <= NN) g_off[j] = run;
        if (j < NN) run += g_degi[j];
    }
}

__global__ void k_build(const int* __restrict__ src, const int* __restrict__ dst) {
    int e = blockIdx.x * blockDim.x + threadIdx.x;
    if (e >= NE) return;
    int p = atomicAdd(&g_cursor[dst[e]], 1);
    g_csr[p] = src[e];
}

// ---------------------------------------------------------------------------
// 4-edge-parallel float4 CSR gather + mean: agg[v] = sum z[nbr] / max(deg,1)
// Warp = 1 node. SLOTS edge slots x (32/SLOTS) float4-lanes. 2x unrolled.
template <int DIM, int SLOTS>
__global__ void k_gather4(const float* __restrict__ z, float* __restrict__ agg) {
    constexpr int F4L = 32 / SLOTS;   // lanes per slot
    constexpr int NF4 = DIM / 4;      // float4 per row
    int gt = blockIdx.x * blockDim.x + threadIdx.x;
    int v = gt >> 5;
    if (v >= NN) return;
    int lane = gt & 31;
    int slot = lane / F4L;
    int f4 = lane % F4L;
    bool act = (f4 < NF4);

    int beg = g_off[v];
    int end = g_off[v + 1];
    float4 acc = make_float4(0.f, 0.f, 0.f, 0.f);

    int e = beg;
    for (; e + 2 * SLOTS <= end; e += 2 * SLOTS) {
        int s0 = g_csr[e + slot];
        int s1 = g_csr[e + SLOTS + slot];
        if (act) {
            float4 t0 = __ldg(reinterpret_cast<const float4*>(z + (size_t)s0 * DIM) + f4);
            float4 t1 = __ldg(reinterpret_cast<const float4*>(z + (size_t)s1 * DIM) + f4);
            acc.x += t0.x + t1.x;
            acc.y += t0.y + t1.y;
            acc.z += t0.z + t1.z;
            acc.w += t0.w + t1.w;
        }
    }
    for (; e < end; e += SLOTS) {
        int myE = e + slot;
        if (myE < end && act) {
            int s0 = g_csr[myE];
            float4 t0 = __ldg(reinterpret_cast<const float4*>(z + (size_t)s0 * DIM) + f4);
            acc.x += t0.x;
            acc.y += t0.y;
            acc.z += t0.z;
            acc.w += t0.w;
        }
    }
    // reduce across slots
#pragma unroll
    for (int m = F4L; m < 32; m <<= 1) {
        acc.x += __shfl_xor_sync(0xFFFFFFFFu, acc.x, m);
        acc.y += __shfl_xor_sync(0xFFFFFFFFu, acc.y, m);
        acc.z += __shfl_xor_sync(0xFFFFFFFFu, acc.z, m);
        acc.w += __shfl_xor_sync(0xFFFFFFFFu, acc.w, m);
    }
    float inv = 1.0f / fmaxf((float)(end - beg), 1.0f);
    if (slot == 0 && act) {
        float4 o = make_float4(acc.x * inv, acc.y * inv, acc.z * inv, acc.w * inv);
        reinterpret_cast<float4*>(agg + (size_t)v * DIM)[f4] = o;
    }
}

// scalar gather for tiny DIM (=5)
template <int DIM>
__global__ void k_gatherS(const float* __restrict__ z, float* __restrict__ agg) {
    int gt = blockIdx.x * blockDim.x + threadIdx.x;
    int v = gt >> 5;
    int lane = gt & 31;
    if (v >= NN) return;
    int beg = g_off[v];
    int end = g_off[v + 1];
    float acc = 0.0f;
    int e = beg;
    for (; e + 2 <= end; e += 2) {
        int s0 = g_csr[e];
        int s1 = g_csr[e + 1];
        if (lane < DIM)
            acc += z[(size_t)s0 * DIM + lane] + z[(size_t)s1 * DIM + lane];
    }
    if (e < end && lane < DIM) acc += z[(size_t)g_csr[e] * DIM + lane];
    float inv = 1.0f / fmaxf((float)(end - beg), 1.0f);
    if (lane < DIM) agg[(size_t)v * DIM + lane] = acc * inv;
}

// ---------------------------------------------------------------------------
// Register-tiled projection: each thread -> float4 of outputs x NV nodes.
// out = act( h@W  + (ADD_AGG ? agg + bias : 0) )
template <int DIN, int DOUT, int NV, bool ADD_AGG, bool RELU>
__global__ void k_proj(const float* __restrict__ h, const float* __restrict__ W,
                       const float* __restrict__ agg, const float* __restrict__ bias,
                       float* __restrict__ out) {
    constexpr int OG = DOUT / 4;
    long long t = (long long)blockIdx.x * blockDim.x + threadIdx.x;
    int oq = (int)(t % OG);
    long long ng = t / OG;
    int n0 = (int)(ng * NV);
    if (n0 >= NN) return;

    float4 acc[NV];
#pragma unroll
    for (int i = 0; i < NV; i++) {
        int node = min(n0 + i, NN - 1);
        if (ADD_AGG) {
            float4 b4 = __ldg(reinterpret_cast<const float4*>(bias) + oq);
            float4 a4 = __ldg(reinterpret_cast<const float4*>(agg + (size_t)node * DOUT) + oq);
            acc[i] = make_float4(b4.x + a4.x, b4.y + a4.y, b4.z + a4.z, b4.w + a4.w);
        } else {
            acc[i] = make_float4(0.f, 0.f, 0.f, 0.f);
        }
    }

#pragma unroll
    for (int k = 0; k < DIN; k += 4) {
        float4 w0 = __ldg(reinterpret_cast<const float4*>(W + (size_t)(k + 0) * DOUT) + oq);
        float4 w1 = __ldg(reinterpret_cast<const float4*>(W + (size_t)(k + 1) * DOUT) + oq);
        float4 w2 = __ldg(reinterpret_cast<const float4*>(W + (size_t)(k + 2) * DOUT) + oq);
        float4 w3 = __ldg(reinterpret_cast<const float4*>(W + (size_t)(k + 3) * DOUT) + oq);
#pragma unroll
        for (int i = 0; i < NV; i++) {
            int node = min(n0 + i, NN - 1);
            float4 hv = __ldg(reinterpret_cast<const float4*>(h + (size_t)node * DIN) + (k >> 2));
            acc[i].x = fmaf(hv.x, w0.x, fmaf(hv.y, w1.x, fmaf(hv.z, w2.x, fmaf(hv.w, w3.x, acc[i].x))));
            acc[i].y = fmaf(hv.x, w0.y, fmaf(hv.y, w1.y, fmaf(hv.z, w2.y, fmaf(hv.w, w3.y, acc[i].y))));
            acc[i].z = fmaf(hv.x, w0.z, fmaf(hv.y, w1.z, fmaf(hv.z, w2.z, fmaf(hv.w, w3.z, acc[i].z))));
            acc[i].w = fmaf(hv.x, w0.w, fmaf(hv.y, w1.w, fmaf(hv.z, w2.w, fmaf(hv.w, w3.w, acc[i].w))));
        }
    }

#pragma unroll
    for (int i = 0; i < NV; i++) {
        if (n0 + i < NN) {
            float4 r = acc[i];
            if (RELU) {
                r.x = fmaxf(r.x, 0.f); r.y = fmaxf(r.y, 0.f);
                r.z = fmaxf(r.z, 0.f); r.w = fmaxf(r.w, 0.f);
            }
            reinterpret_cast<float4*>(out + (size_t)(n0 + i) * DOUT)[oq] = r;
        }
    }
}

// Fused layer-0: out = relu( feat@Ws + agg@Wn + b ), DIN=32, DOUT=128
template <int NV>
__global__ void k_sage0(const float* __restrict__ feat, const float* __restrict__ agg,
                        const float* __restrict__ Ws, const float* __restrict__ Wn,
                        const float* __restrict__ bias, float* __restrict__ out) {
    constexpr int DIN = 32, DOUT = 128, OG = 32;
    long long t = (long long)blockIdx.x * blockDim.x + threadIdx.x;
    int oq = (int)(t % OG);
    long long ng = t / OG;
    int n0 = (int)(ng * NV);
    if (n0 >= NN) return;

    float4 b4 = __ldg(reinterpret_cast<const float4*>(bias) + oq);
    float4 acc[NV];
#pragma unroll
    for (int i = 0; i < NV; i++) acc[i] = b4;

#pragma unroll
    for (int k = 0; k < DIN; k += 4) {
        float4 ws0 = __ldg(reinterpret_cast<const float4*>(Ws + (size_t)(k + 0) * DOUT) + oq);
        float4 ws1 = __ldg(reinterpret_cast<const float4*>(Ws + (size_t)(k + 1) * DOUT) + oq);
        float4 ws2 = __ldg(reinterpret_cast<const float4*>(Ws + (size_t)(k + 2) * DOUT) + oq);
        float4 ws3 = __ldg(reinterpret_cast<const float4*>(Ws + (size_t)(k + 3) * DOUT) + oq);
        float4 wn0 = __ldg(reinterpret_cast<const float4*>(Wn + (size_t)(k + 0) * DOUT) + oq);
        float4 wn1 = __ldg(reinterpret_cast<const float4*>(Wn + (size_t)(k + 1) * DOUT) + oq);
        float4 wn2 = __ldg(reinterpret_cast<const float4*>(Wn + (size_t)(k + 2) * DOUT) + oq);
        float4 wn3 = __ldg(reinterpret_cast<const float4*>(Wn + (size_t)(k + 3) * DOUT) + oq);
#pragma unroll
        for (int i = 0; i < NV; i++) {
            int node = min(n0 + i, NN - 1);
            float4 hv = __ldg(reinterpret_cast<const float4*>(feat + (size_t)node * DIN) + (k >> 2));
            float4 av = __ldg(reinterpret_cast<const float4*>(agg + (size_t)node * DIN) + (k >> 2));
            acc[i].x = fmaf(hv.x, ws0.x, fmaf(hv.y, ws1.x, fmaf(hv.z, ws2.x, fmaf(hv.w, ws3.x, acc[i].x))));
            acc[i].y = fmaf(hv.x, ws0.y, fmaf(hv.y, ws1.y, fmaf(hv.z, ws2.y, fmaf(hv.w, ws3.y, acc[i].y))));
            acc[i].z = fmaf(hv.x, ws0.z, fmaf(hv.y, ws1.z, fmaf(hv.z, ws2.z, fmaf(hv.w, ws3.z, acc[i].z))));
            acc[i].w = fmaf(hv.x, ws0.w, fmaf(hv.y, ws1.w, fmaf(hv.z, ws2.w, fmaf(hv.w, ws3.w, acc[i].w))));
            acc[i].x = fmaf(av.x, wn0.x, fmaf(av.y, wn1.x, fmaf(av.z, wn2.x, fmaf(av.w, wn3.x, acc[i].x))));
            acc[i].y = fmaf(av.x, wn0.y, fmaf(av.y, wn1.y, fmaf(av.z, wn2.y, fmaf(av.w, wn3.y, acc[i].y))));
            acc[i].z = fmaf(av.x, wn0.z, fmaf(av.y, wn1.z, fmaf(av.z, wn2.z, fmaf(av.w, wn3.z, acc[i].z))));
            acc[i].w = fmaf(av.x, wn0.w, fmaf(av.y, wn1.w, fmaf(av.z, wn2.w, fmaf(av.w, wn3.w, acc[i].w))));
        }
    }

#pragma unroll
    for (int i = 0; i < NV; i++) {
        if (n0 + i < NN) {
            float4 r = acc[i];
            r.x = fmaxf(r.x, 0.f); r.y = fmaxf(r.y, 0.f);
            r.z = fmaxf(r.z, 0.f); r.w = fmaxf(r.w, 0.f);
            reinterpret_cast<float4*>(out + (size_t)(n0 + i) * DOUT)[oq] = r;
        }
    }
}

// ---------------------------------------------------------------------------
// scalar fallbacks for tiny (DOUT=5) layer
template <int DIN, int DOUT>
__global__ void k_gemmS(const float* __restrict__ h, const float* __restrict__ W,
                        float* __restrict__ z) {
    long long idx = (long long)blockIdx.x * blockDim.x + threadIdx.x;
    if (idx >= (long long)NN * DOUT) return;
    int v = (int)(idx / DOUT);
    int o = (int)(idx % DOUT);
    const float* hrow = h + (size_t)v * DIN;
    float acc = 0.0f;
#pragma unroll
    for (int k = 0; k < DIN; k++) acc = fmaf(hrow[k], W[k * DOUT + o], acc);
    z[idx] = acc;
}

template <int DIN, int DOUT, bool RELU>
__global__ void k_postS(const float* __restrict__ h, const float* __restrict__ aggn,
                        const float* __restrict__ Ws, const float* __restrict__ bias,
                        float* __restrict__ out) {
    long long idx = (long long)blockIdx.x * blockDim.x + threadIdx.x;
    if (idx >= (long long)NN * DOUT) return;
    int v = (int)(idx / DOUT);
    int o = (int)(idx % DOUT);
    const float* hrow = h + (size_t)v * DIN;
    float acc = bias[o] + aggn[idx];
#pragma unroll
    for (int k = 0; k < DIN; k++) acc = fmaf(hrow[k], Ws[k * DOUT + o], acc);
    out[idx] = RELU ? fmaxf(acc, 0.0f) : acc;
}

// ---------------------------------------------------------------------------
__global__ void k_cnt(const int* __restrict__ gid) {
    int v = blockIdx.x * blockDim.x + threadIdx.x;
    if (v < NN) atomicAdd(&g_cnt[gid[v]], 1.0f);
}

__global__ void k_accum(const float* __restrict__ h, const int* __restrict__ gid,
                        float* __restrict__ out) {
    int idx = blockIdx.x * blockDim.x + threadIdx.x;
    if (idx >= NN * 5) return;
    atomicAdd(&out[gid[idx / 5] * 5 + (idx % 5)], h[idx]);
}

__global__ void k_final(float* __restrict__ out) {
    int i = blockIdx.x * blockDim.x + threadIdx.x;
    if (i < NG * 5) out[i] /= fmaxf(g_cnt[i / 5], 1.0f);
}

// ---------------------------------------------------------------------------
static inline int blks(long long n, int t) { return (int)((n + t - 1) / t); }

extern "C" void kernel_launch(void* const* d_in, const int* in_sizes, int n_in,
                              void* d_out, int out_size) {
    const float* feat = (const float*)d_in[0];
    const int* src = (const int*)d_in[1];
    const int* dst = (const int*)d_in[2];
    const int* gid = (const int*)d_in[3];
    const float* Ws0 = (const float*)d_in[4];
    const float* Wn0 = (const float*)d_in[5];
    const float* b0  = (const float*)d_in[6];
    const float* Ws1 = (const float*)d_in[7];
    const float* Wn1 = (const float*)d_in[8];
    const float* b1  = (const float*)d_in[9];
    const float* Ws2 = (const float*)d_in[10];
    const float* Wn2 = (const float*)d_in[11];
    const float* b2  = (const float*)d_in[12];
    const float* Ws3 = (const float*)d_in[13];
    const float* Wn3 = (const float*)d_in[14];
    const float* b3  = (const float*)d_in[15];
    float* out = (float*)d_out;

    float *bufA, *bufB, *z, *agg, *cnt;
    int *degi, *off, *cursor;
    cudaGetSymbolAddress((void**)&bufA, g_bufA);
    cudaGetSymbolAddress((void**)&bufB, g_bufB);
    cudaGetSymbolAddress((void**)&z, g_z);
    cudaGetSymbolAddress((void**)&agg, g_agg);
    cudaGetSymbolAddress((void**)&cnt, g_cnt);
    cudaGetSymbolAddress((void**)&degi, g_degi);
    cudaGetSymbolAddress((void**)&off, g_off);
    cudaGetSymbolAddress((void**)&cursor, g_cursor);

    const int T = 256;

    // ---- CSR build ----
    cudaMemsetAsync(degi, 0, NN * sizeof(int));
    k_degree<<<blks(NE, T), T>>>(dst);
    k_scan<<<1, 1024>>>();
    cudaMemcpyAsync(cursor, off, NN * sizeof(int), cudaMemcpyDeviceToDevice);
    k_build<<<blks(NE, T), T>>>(src, dst);

    // ---- layer 0: 32 -> 128, relu ----
    k_gather4<32, 4><<<blks((long long)NN * 32, T), T>>>(feat, agg);
    {
        long long th = (long long)((NN + 3) / 4) * 32;
        k_sage0<4><<<blks(th, T), T>>>(feat, agg, Ws0, Wn0, b0, bufA);
    }

    // ---- layer 1: 128 -> 48, relu ----
    {
        long long th = (long long)((NN + 7) / 8) * 12;
        k_proj<128, 48, 8, false, false><<<blks(th, T), T>>>(bufA, Wn1, nullptr, nullptr, z);
    }
    k_gather4<48, 2><<<blks((long long)NN * 32, T), T>>>(z, agg);
    {
        long long th = (long long)((NN + 7) / 8) * 12;
        k_proj<128, 48, 8, true, true><<<blks(th, T), T>>>(bufA, Ws1, agg, b1, bufB);
    }

    // ---- layer 2: 48 -> 28, relu ----
    {
        long long th = (long long)((NN + 7) / 8) * 7;
        k_proj<48, 28, 8, false, false><<<blks(th, T), T>>>(bufB, Wn2, nullptr, nullptr, z);
    }
    k_gather4<28, 4><<<blks((long long)NN * 32, T), T>>>(z, agg);
    {
        long long th = (long long)((NN + 7) / 8) * 7;
        k_proj<48, 28, 8, true, true><<<blks(th, T), T>>>(bufB, Ws2, agg, b2, bufA);
    }

    // ---- layer 3: 28 -> 5, linear (scalar path) ----
    k_gemmS<28, 5><<<blks((long long)NN * 5, T), T>>>(bufA, Wn3, z);
    k_gatherS<5><<<blks((long long)NN * 32, T), T>>>(z, agg);
    k_postS<28, 5, false><<<blks((long long)NN * 5, T), T>>>(bufA, agg, Ws3, b3, bufB);

    // ---- readout ----
    cudaMemsetAsync(out, 0, NG * 5 * sizeof(float));
    cudaMemsetAsync(cnt, 0, NG * sizeof(float));
    k_cnt<<<blks(NN, T), T>>>(gid);
    k_accum<<<blks((long long)NN * 5, T), T>>>(bufB, gid, out);
    k_final<<<blks(NG * 5, T), T>>>(out);
}